// round 8
// baseline (speedup 1.0000x reference)
#include <cuda_runtime.h>
#include <cstdint>

// GraphSAGE fused layer kernel for GB300 (sm_103a).  R7: BM=128 with 8x8
// register tile per thread (smem bytes/FFMA2: 3 -> 2; A broadcast, B as
// adjacent-column-pair LDS.128), W staged in smem one k-half at a time
// (64 KB, reloaded per phase from L2), gather fused in phase 1 with a
// 4-node quad + depth-2 LDG ring per warp.
//
// Layer: Z = [h | mean_k h[idx_k]] @ W + b ; h' = relu(Z).

#define N_NODES 100000
#define D 128
#define KNE 16
#define BM 128
#define NTHREADS 256
#define SA 132                            // A row stride (floats): bank skew, 16B mult
#define TILES ((N_NODES + BM - 1) / BM)   // 782
#define GRID 152

typedef unsigned long long ull;

// Inter-layer activation scratch (51.2 MB). __device__ global: allocation-free.
__device__ float g_h[(size_t)N_NODES * D];

__device__ __forceinline__ void ffma2(ull& d, ull a, ull b) {
    asm("fma.rn.f32x2 %0, %1, %2, %0;" : "+l"(d) : "l"(a), "l"(b));
}
__device__ __forceinline__ ull add2(ull a, ull b) {
    ull r; asm("add.rn.f32x2 %0, %1, %2;" : "=l"(r) : "l"(a), "l"(b)); return r;
}
__device__ __forceinline__ ull mul2(ull a, ull b) {
    ull r; asm("mul.rn.f32x2 %0, %1, %2;" : "=l"(r) : "l"(a), "l"(b)); return r;
}
__device__ __forceinline__ ull pack2(float x) {
    ull r; asm("mov.b64 %0, {%1, %1};" : "=l"(r) : "f"(x)); return r;
}
__device__ __forceinline__ void unpack2(ull v, float& lo, float& hi) {
    asm("mov.b64 {%0, %1}, %2;" : "=f"(lo), "=f"(hi) : "l"(v));
}

// Load one k-half of W (rows k0..k0+127) into smem, k-pair interleaved:
// Wi[k2*256 + c*2 + p] = W[k0 + 2*k2 + p][c]
__device__ __forceinline__ void load_W_half(float* Wi_s, const float* W, int k0, int tid) {
    for (int i = tid; i < 64 * 32; i += NTHREADS) {
        int k2 = i >> 5, c4 = i & 31;
        float4 w0 = ((const float4*)(W + (size_t)(k0 + 2 * k2)     * 128))[c4];
        float4 w1 = ((const float4*)(W + (size_t)(k0 + 2 * k2 + 1) * 128))[c4];
        float* dst = Wi_s + k2 * 256 + c4 * 8;
        ((float4*)dst)[0] = make_float4(w0.x, w1.x, w0.y, w1.y);
        ((float4*)dst)[1] = make_float4(w0.z, w1.z, w0.w, w1.w);
    }
}

template <bool RELU>
__global__ void __launch_bounds__(NTHREADS, 1)
sage_layer(const float* __restrict__ h_in,
           const int*   __restrict__ nidx,
           const float* __restrict__ W,     // [256][128] row-major
           const float* __restrict__ bias,  // [128]
           float*       __restrict__ out)   // [N][128]
{
    extern __shared__ float smem[];
    float* Wi_s   = smem;                       // one k-half interleaved: 64 KB
    float* A_self = smem + 64 * 256;            // [128][SA]  66 KB
    float* A_agg  = A_self + BM * SA;           // [128][SA]  66 KB
    int*   idx_s  = (int*)(A_agg + BM * SA);    // [128][16]   8 KB

    const int tid  = threadIdx.x;
    const int warp = tid >> 5;
    const int lane = tid & 31;
    const int tx   = tid & 15;                  // column-pair group
    const int ty   = tid >> 4;                  // row group

    float2 bv2[4];
    #pragma unroll
    for (int m = 0; m < 4; m++)
        bv2[m] = *(const float2*)(bias + 32 * m + 2 * tx);

    const ull s16 = pack2(1.0f / 16.0f);

    for (int tile = blockIdx.x; tile < TILES; tile += gridDim.x) {
        const int base = tile * BM;

        __syncthreads();   // protect smem vs previous tile readers

        load_W_half(Wi_s, W, 0, tid);

        // ---- self features -> A_self ----
        #pragma unroll
        for (int i = tid; i < BM * 32; i += NTHREADS) {
            int node = i >> 5, c4 = i & 31;
            if (base + node < N_NODES)
                ((float4*)(A_self + node * SA))[c4] =
                    ((const float4*)(h_in + (size_t)(base + node) * D))[c4];
        }
        // ---- neighbor indices -> idx_s (zero-fill invalid nodes) ----
        #pragma unroll
        for (int i = tid; i < BM * KNE / 4; i += NTHREADS) {
            int node = i >> 2;
            int4 v = make_int4(0, 0, 0, 0);
            if (base + node < N_NODES)
                v = ((const int4*)(nidx + (size_t)base * KNE))[i];
            ((int4*)idx_s)[i] = v;
        }
        __syncthreads();

        ull acc[8][8];
        #pragma unroll
        for (int i = 0; i < 8; i++)
            #pragma unroll
            for (int m = 0; m < 8; m++) acc[i][m] = 0ULL;

        // ---- gather state: warp owns nodes warp*16..+15 as 4 quads of 4 nodes,
        //      16 steps per quad; one step per k2 iteration, depth-2 LDG ring.
        ull gx[4], gy[4];
        #pragma unroll
        for (int t = 0; t < 4; t++) { gx[t] = 0; gy[t] = 0; }
        float4 bufE[4], bufO[4];

        // prologue: issue steps 0 (quad 0, j=0) and 1 (quad 0, j=1)
        {
            const int n0 = warp * 16;
            #pragma unroll
            for (int t = 0; t < 4; t++) {
                bufE[t] = ((const float4*)(h_in + (size_t)idx_s[(n0 + t) * 16 + 0] * D))[lane];
                bufO[t] = ((const float4*)(h_in + (size_t)idx_s[(n0 + t) * 16 + 1] * D))[lane];
            }
        }

        // ---- phase 1: GEMM self half (k=0..127) + fused gather ----
        #pragma unroll 2
        for (int k2 = 0; k2 < 64; k2++) {
            float4* buf = (k2 & 1) ? bufO : bufE;
            // consume step k2 (loaded 2 iterations ago)
            #pragma unroll
            for (int t = 0; t < 4; t++) {
                ulonglong2 p = *(ulonglong2*)&buf[t];
                gx[t] = add2(gx[t], p.x);
                gy[t] = add2(gy[t], p.y);
            }
            // issue step k2+2
            if (k2 < 62) {
                int s  = k2 + 2;
                int n0 = warp * 16 + (s >> 4) * 4;
                int j  = s & 15;
                #pragma unroll
                for (int t = 0; t < 4; t++)
                    buf[t] = ((const float4*)(h_in + (size_t)idx_s[(n0 + t) * 16 + j] * D))[lane];
            }
            // quad boundary: write means, reset
            if ((k2 & 15) == 15) {
                int n0 = warp * 16 + (k2 >> 4) * 4;
                #pragma unroll
                for (int t = 0; t < 4; t++) {
                    ulonglong2 r;
                    r.x = mul2(gx[t], s16);
                    r.y = mul2(gy[t], s16);
                    *(ulonglong2*)(A_agg + (n0 + t) * SA + lane * 4) = r;
                    gx[t] = 0; gy[t] = 0;
                }
            }
            // GEMM body
            const float* wrow = Wi_s + k2 * 256;
            ulonglong2 b[4];
            #pragma unroll
            for (int m = 0; m < 4; m++)
                b[m] = *(const ulonglong2*)(wrow + 4 * tx + 64 * m);
            ull a[8];
            #pragma unroll
            for (int i = 0; i < 8; i++)
                a[i] = *(const ull*)(A_self + (ty + 16 * i) * SA + k2 * 2);
            #pragma unroll
            for (int i = 0; i < 8; i++)
                #pragma unroll
                for (int m = 0; m < 4; m++) {
                    ffma2(acc[i][2 * m],     a[i], b[m].x);
                    ffma2(acc[i][2 * m + 1], a[i], b[m].y);
                }
        }
        __syncthreads();   // A_agg complete; all warps done reading Wi half1

        load_W_half(Wi_s, W, 128, tid);
        __syncthreads();

        // ---- phase 2: GEMM agg half (k=128..255) ----
        #pragma unroll 4
        for (int k2 = 0; k2 < 64; k2++) {
            const float* wrow = Wi_s + k2 * 256;
            ulonglong2 b[4];
            #pragma unroll
            for (int m = 0; m < 4; m++)
                b[m] = *(const ulonglong2*)(wrow + 4 * tx + 64 * m);
            ull a[8];
            #pragma unroll
            for (int i = 0; i < 8; i++)
                a[i] = *(const ull*)(A_agg + (ty + 16 * i) * SA + k2 * 2);
            #pragma unroll
            for (int i = 0; i < 8; i++)
                #pragma unroll
                for (int m = 0; m < 4; m++) {
                    ffma2(acc[i][2 * m],     a[i], b[m].x);
                    ffma2(acc[i][2 * m + 1], a[i], b[m].y);
                }
        }

        // ---- epilogue: combine even/odd-k halves, +bias, relu, store ----
        #pragma unroll
        for (int i = 0; i < 8; i++) {
            int r = ty + 16 * i;
            if (base + r < N_NODES) {
                float* orow = out + (size_t)(base + r) * D + 2 * tx;
                #pragma unroll
                for (int m = 0; m < 4; m++) {
                    float lo0, hi0, lo1, hi1;
                    unpack2(acc[i][2 * m],     lo0, hi0);
                    unpack2(acc[i][2 * m + 1], lo1, hi1);
                    float v0 = lo0 + hi0 + bv2[m].x;
                    float v1 = lo1 + hi1 + bv2[m].y;
                    if (RELU) { v0 = fmaxf(v0, 0.0f); v1 = fmaxf(v1, 0.0f); }
                    *(float2*)(orow + 32 * m) = make_float2(v0, v1);
                }
            }
        }
    }
}

extern "C" void kernel_launch(void* const* d_in, const int* in_sizes, int n_in,
                              void* d_out, int out_size) {
    const float* feats = (const float*)d_in[0];
    const int*   nidx  = (const int*)d_in[1];
    const float* Ws    = (const float*)d_in[2];
    const float* bs    = (const float*)d_in[3];
    float*       out   = (float*)d_out;

    void* hbuf = nullptr;
    cudaGetSymbolAddress(&hbuf, g_h);
    float* h1 = (float*)hbuf;

    const size_t SMEM = (size_t)(64 * 256 + 2 * BM * SA) * sizeof(float)
                      + (size_t)BM * KNE * sizeof(int);   // 208896 B
    cudaFuncSetAttribute(sage_layer<true>,  cudaFuncAttributeMaxDynamicSharedMemorySize, (int)SMEM);
    cudaFuncSetAttribute(sage_layer<false>, cudaFuncAttributeMaxDynamicSharedMemorySize, (int)SMEM);

    // layer 0: feats -> g_h = relu(cat @ W0 + b0)
    sage_layer<true><<<GRID, NTHREADS, SMEM>>>(feats, nidx, Ws, bs, h1);
    // layer 1: g_h -> out = cat @ W1 + b1  (pre-relu)
    sage_layer<false><<<GRID, NTHREADS, SMEM>>>(
        h1, nidx + (size_t)N_NODES * KNE, Ws + 256 * 128, bs + 128, out);
}

// round 9
// speedup vs baseline: 1.0573x; 1.0573x over previous
#include <cuda_runtime.h>
#include <cstdint>

// GraphSAGE fused layer kernel for GB300 (sm_103a).  R8: occupancy fix —
// 384 threads (3 warps/SMSP) with the spill-free 4x8 register tile
// (regs ~140 <= 170 budget), BM=96, W staged one k-half at a time,
// gather fused into phase-1 (2 nodes/warp concurrent, depth-2 LDG ring).
//
// Layer: Z = [h | mean_k h[idx_k]] @ W + b ; h' = relu(Z).

#define N_NODES 100000
#define D 128
#define KNE 16
#define BM 96
#define NTHREADS 384
#define SA 132                            // A row stride (floats): bank skew, 16B mult
#define TILES ((N_NODES + BM - 1) / BM)   // 1042
#define GRID 152

typedef unsigned long long ull;

// Inter-layer activation scratch (51.2 MB). __device__ global: allocation-free.
__device__ float g_h[(size_t)N_NODES * D];

__device__ __forceinline__ void ffma2(ull& d, ull a, ull b) {
    asm("fma.rn.f32x2 %0, %1, %2, %0;" : "+l"(d) : "l"(a), "l"(b));
}
__device__ __forceinline__ ull add2(ull a, ull b) {
    ull r; asm("add.rn.f32x2 %0, %1, %2;" : "=l"(r) : "l"(a), "l"(b)); return r;
}
__device__ __forceinline__ ull mul2(ull a, ull b) {
    ull r; asm("mul.rn.f32x2 %0, %1, %2;" : "=l"(r) : "l"(a), "l"(b)); return r;
}
__device__ __forceinline__ ull pack2(float x) {
    ull r; asm("mov.b64 %0, {%1, %1};" : "=l"(r) : "f"(x)); return r;
}
__device__ __forceinline__ void unpack2(ull v, float& lo, float& hi) {
    asm("mov.b64 {%0, %1}, %2;" : "=f"(lo), "=f"(hi) : "l"(v));
}

// Load one k-half of W (rows k0..k0+127) into smem, k-pair interleaved:
// Wi[k2*256 + c*2 + p] = W[k0 + 2*k2 + p][c]
__device__ __forceinline__ void load_W_half(float* Wi_s, const float* W, int k0, int tid) {
    for (int i = tid; i < 64 * 32; i += NTHREADS) {
        int k2 = i >> 5, c4 = i & 31;
        float4 w0 = ((const float4*)(W + (size_t)(k0 + 2 * k2)     * 128))[c4];
        float4 w1 = ((const float4*)(W + (size_t)(k0 + 2 * k2 + 1) * 128))[c4];
        float* dst = Wi_s + k2 * 256 + c4 * 8;
        ((float4*)dst)[0] = make_float4(w0.x, w1.x, w0.y, w1.y);
        ((float4*)dst)[1] = make_float4(w0.z, w1.z, w0.w, w1.w);
    }
}

template <bool RELU>
__global__ void __launch_bounds__(NTHREADS, 1)
sage_layer(const float* __restrict__ h_in,
           const int*   __restrict__ nidx,
           const float* __restrict__ W,     // [256][128] row-major
           const float* __restrict__ bias,  // [128]
           float*       __restrict__ out)   // [N][128]
{
    extern __shared__ float smem[];
    float* Wi_s   = smem;                       // one k-half interleaved: 64 KB
    float* A_self = smem + 64 * 256;            // [96][SA]  50.7 KB
    float* A_agg  = A_self + BM * SA;           // [96][SA]  50.7 KB
    int*   idx_s  = (int*)(A_agg + BM * SA);    // [96][16]   6 KB

    const int tid  = threadIdx.x;
    const int warp = tid >> 5;                  // 0..11
    const int lane = tid & 31;
    const int tx   = tid & 15;                  // col-pair group: cols {2tx,2tx+1}+32m
    const int ty   = tid >> 4;                  // 0..23; rows ty + 24*i

    float2 bv2[4];
    #pragma unroll
    for (int m = 0; m < 4; m++)
        bv2[m] = *(const float2*)(bias + 32 * m + 2 * tx);

    const ull s16 = pack2(1.0f / 16.0f);

    for (int tile = blockIdx.x; tile < TILES; tile += gridDim.x) {
        const int base = tile * BM;

        __syncthreads();   // protect smem vs previous tile readers

        load_W_half(Wi_s, W, 0, tid);

        // ---- self features -> A_self ----
        #pragma unroll
        for (int i = tid; i < BM * 32; i += NTHREADS) {
            int node = i >> 5, c4 = i & 31;
            if (base + node < N_NODES)
                ((float4*)(A_self + node * SA))[c4] =
                    ((const float4*)(h_in + (size_t)(base + node) * D))[c4];
        }
        // ---- neighbor indices -> idx_s (zero-fill invalid nodes) ----
        {
            int i = tid;               // BM*KNE/4 = 384 int4 loads, one per thread
            int node = i >> 2;
            int4 v = make_int4(0, 0, 0, 0);
            if (base + node < N_NODES)
                v = ((const int4*)(nidx + (size_t)base * KNE))[i];
            ((int4*)idx_s)[i] = v;
        }
        __syncthreads();

        ull acc[4][8];
        #pragma unroll
        for (int i = 0; i < 4; i++)
            #pragma unroll
            for (int m = 0; m < 8; m++) acc[i][m] = 0ULL;

        // ---- gather state: warp owns nodes warp*8..+7 as 4 pairs; 16 steps/pair,
        //      one step per k2 iteration (2 nodes concurrent), depth-2 LDG ring.
        ull g0x = 0, g0y = 0, g1x = 0, g1y = 0;
        float4 bufA[2], bufB[2];

        // prologue: issue steps 0,1 (pair 0)
        {
            const int n0 = warp * 8;
            #pragma unroll
            for (int j = 0; j < 2; j++) {
                bufA[j] = ((const float4*)(h_in + (size_t)idx_s[n0 * 16 + j]      * D))[lane];
                bufB[j] = ((const float4*)(h_in + (size_t)idx_s[n0 * 16 + 16 + j] * D))[lane];
            }
        }

        // ---- phase 1: GEMM self half (k=0..127) + fused gather ----
        #pragma unroll 2
        for (int k2 = 0; k2 < 64; k2++) {
            const int slot = k2 & 1;
            // consume step k2 (issued 2 iterations ago); it belongs to pair k2>>4
            {
                ulonglong2 pA = *(ulonglong2*)&bufA[slot];
                ulonglong2 pB = *(ulonglong2*)&bufB[slot];
                g0x = add2(g0x, pA.x); g0y = add2(g0y, pA.y);
                g1x = add2(g1x, pB.x); g1y = add2(g1y, pB.y);
            }
            // issue step k2+2 into the freed slot
            if (k2 < 62) {
                int s  = k2 + 2;
                int n0 = warp * 8 + (s >> 4) * 2;
                int j  = s & 15;
                bufA[slot] = ((const float4*)(h_in + (size_t)idx_s[n0 * 16 + j]      * D))[lane];
                bufB[slot] = ((const float4*)(h_in + (size_t)idx_s[n0 * 16 + 16 + j] * D))[lane];
            }
            // pair boundary: write means, reset
            if ((k2 & 15) == 15) {
                int n0 = warp * 8 + (k2 >> 4) * 2;
                {
                    ulonglong2 r; r.x = mul2(g0x, s16); r.y = mul2(g0y, s16);
                    *(ulonglong2*)(A_agg + n0 * SA + lane * 4) = r;
                }
                {
                    ulonglong2 r; r.x = mul2(g1x, s16); r.y = mul2(g1y, s16);
                    *(ulonglong2*)(A_agg + (n0 + 1) * SA + lane * 4) = r;
                }
                g0x = 0; g0y = 0; g1x = 0; g1y = 0;
            }
            // GEMM body (self half)
            const float* wrow = Wi_s + k2 * 256;
            ulonglong2 b[4];
            #pragma unroll
            for (int m = 0; m < 4; m++)
                b[m] = *(const ulonglong2*)(wrow + 4 * tx + 64 * m);
            ull a[4];
            #pragma unroll
            for (int i = 0; i < 4; i++)
                a[i] = *(const ull*)(A_self + (ty + 24 * i) * SA + k2 * 2);
            #pragma unroll
            for (int i = 0; i < 4; i++)
                #pragma unroll
                for (int m = 0; m < 4; m++) {
                    ffma2(acc[i][2 * m],     a[i], b[m].x);
                    ffma2(acc[i][2 * m + 1], a[i], b[m].y);
                }
        }
        __syncthreads();   // A_agg complete; all warps done with W half 1

        load_W_half(Wi_s, W, 128, tid);
        __syncthreads();

        // ---- phase 2: GEMM agg half (k=128..255) ----
        #pragma unroll 4
        for (int k2 = 0; k2 < 64; k2++) {
            const float* wrow = Wi_s + k2 * 256;
            ulonglong2 b[4];
            #pragma unroll
            for (int m = 0; m < 4; m++)
                b[m] = *(const ulonglong2*)(wrow + 4 * tx + 64 * m);
            ull a[4];
            #pragma unroll
            for (int i = 0; i < 4; i++)
                a[i] = *(const ull*)(A_agg + (ty + 24 * i) * SA + k2 * 2);
            #pragma unroll
            for (int i = 0; i < 4; i++)
                #pragma unroll
                for (int m = 0; m < 4; m++) {
                    ffma2(acc[i][2 * m],     a[i], b[m].x);
                    ffma2(acc[i][2 * m + 1], a[i], b[m].y);
                }
        }

        // ---- epilogue: combine even/odd-k halves, +bias, relu, store ----
        #pragma unroll
        for (int i = 0; i < 4; i++) {
            int r = ty + 24 * i;
            if (base + r < N_NODES) {
                float* orow = out + (size_t)(base + r) * D + 2 * tx;
                #pragma unroll
                for (int m = 0; m < 4; m++) {
                    float lo0, hi0, lo1, hi1;
                    unpack2(acc[i][2 * m],     lo0, hi0);
                    unpack2(acc[i][2 * m + 1], lo1, hi1);
                    float v0 = lo0 + hi0 + bv2[m].x;
                    float v1 = lo1 + hi1 + bv2[m].y;
                    if (RELU) { v0 = fmaxf(v0, 0.0f); v1 = fmaxf(v1, 0.0f); }
                    *(float2*)(orow + 32 * m) = make_float2(v0, v1);
                }
            }
        }
    }
}

extern "C" void kernel_launch(void* const* d_in, const int* in_sizes, int n_in,
                              void* d_out, int out_size) {
    const float* feats = (const float*)d_in[0];
    const int*   nidx  = (const int*)d_in[1];
    const float* Ws    = (const float*)d_in[2];
    const float* bs    = (const float*)d_in[3];
    float*       out   = (float*)d_out;

    void* hbuf = nullptr;
    cudaGetSymbolAddress(&hbuf, g_h);
    float* h1 = (float*)hbuf;

    const size_t SMEM = (size_t)(64 * 256 + 2 * BM * SA) * sizeof(float)
                      + (size_t)BM * KNE * sizeof(int);   // 173056 B
    cudaFuncSetAttribute(sage_layer<true>,  cudaFuncAttributeMaxDynamicSharedMemorySize, (int)SMEM);
    cudaFuncSetAttribute(sage_layer<false>, cudaFuncAttributeMaxDynamicSharedMemorySize, (int)SMEM);

    // layer 0: feats -> g_h = relu(cat @ W0 + b0)
    sage_layer<true><<<GRID, NTHREADS, SMEM>>>(feats, nidx, Ws, bs, h1);
    // layer 1: g_h -> out = cat @ W1 + b1  (pre-relu)
    sage_layer<false><<<GRID, NTHREADS, SMEM>>>(
        h1, nidx + (size_t)N_NODES * KNE, Ws + 256 * 128, bs + 128, out);
}

// round 11
// speedup vs baseline: 1.5811x; 1.4954x over previous
#include <cuda_runtime.h>
#include <cuda_bf16.h>
#include <cstdint>

// GraphSAGE on GB300 (sm_103a harness, PTX target sm_103 base).
// R10: tensor cores via classic mma.sync bf16 (m16n8k16) + ldmatrix — no
// 'a'-gated tcgen05. bf16 hi/lo split: D = Ahi*Bhi + Ahi*Blo + Alo*Bhi.
// Warp-specialized persistent kernel: warps 0-7 MMA, warps 8-15 gather
// (overlapped with phase-1). W pre-transposed/split/swizzled per layer by a
// prep kernel into a __device__ image; per-phase smem W load is a memcpy.

#define N_NODES 100000
#define D 128
#define KNE 16
#define BM 128
#define NTHREADS 512
#define TILES ((N_NODES + BM - 1) / BM)   // 782
#define GRID 152

// smem byte offsets (each region: hi then lo, 32768 B apiece)
#define OFF_W     0
#define OFF_SELF  65536
#define OFF_AGG   131072
#define OFF_IDX   196608
#define OFF_BIAS  204800
#define SMEM_TOTAL 205312

typedef unsigned long long ull;

// device scratch: inter-layer activations + prepped W image (allocation-free)
__device__ float g_h[(size_t)N_NODES * D];
__device__ __align__(16) unsigned char g_wt[131072];   // [phase][hi|lo][swizzled 32768]

// ---------------- helpers ----------------
__device__ __forceinline__ uint32_t smem_u32(const void* p) {
    uint32_t a;
    asm("{ .reg .u64 t; cvta.to.shared.u64 t, %1; cvt.u32.u64 %0, t; }" : "=r"(a) : "l"(p));
    return a;
}
__device__ __forceinline__ ull add2(ull a, ull b) {
    ull r; asm("add.rn.f32x2 %0, %1, %2;" : "=l"(r) : "l"(a), "l"(b)); return r;
}
__device__ __forceinline__ void unpack2(ull v, float& lo, float& hi) {
    asm("mov.b64 {%0, %1}, %2;" : "=f"(lo), "=f"(hi) : "l"(v));
}
__device__ __forceinline__ void ldsm4(uint32_t* r, uint32_t addr) {
    asm volatile("ldmatrix.sync.aligned.m8n8.x4.shared.b16 {%0,%1,%2,%3}, [%4];"
        : "=r"(r[0]), "=r"(r[1]), "=r"(r[2]), "=r"(r[3]) : "r"(addr));
}
__device__ __forceinline__ void ldsm2(uint32_t* r, uint32_t addr) {
    asm volatile("ldmatrix.sync.aligned.m8n8.x2.shared.b16 {%0,%1}, [%2];"
        : "=r"(r[0]), "=r"(r[1]) : "r"(addr));
}
__device__ __forceinline__ void mma_bf16(float* d, const uint32_t* a, const uint32_t* b) {
    asm volatile("mma.sync.aligned.m16n8k16.row.col.f32.bf16.bf16.f32 "
        "{%0,%1,%2,%3}, {%4,%5,%6,%7}, {%8,%9}, {%0,%1,%2,%3};"
        : "+f"(d[0]), "+f"(d[1]), "+f"(d[2]), "+f"(d[3])
        : "r"(a[0]), "r"(a[1]), "r"(a[2]), "r"(a[3]), "r"(b[0]), "r"(b[1]));
}
#define BAR_SYNC(id, n)   asm volatile("bar.sync %0, %1;"   :: "r"(id), "r"(n) : "memory")
#define BAR_ARRIVE(id, n) asm volatile("bar.arrive %0, %1;" :: "r"(id), "r"(n) : "memory")

// XOR-swizzled byte offset inside a [128 rows][256 B] tile: bits 4-6 ^= row&7.
__device__ __host__ __forceinline__ uint32_t sw_off(int row, int byte_in_row) {
    return (uint32_t)(row * 256 + (byte_in_row ^ ((row & 7) << 4)));
}

// split 4 floats at (row, col..col+3) into bf16 hi/lo tiles (8 B each).
__device__ __forceinline__ void split_store4(char* hiB, char* loB, int row, int col, float4 v) {
    __nv_bfloat162 h0 = __floats2bfloat162_rn(v.x, v.y);
    __nv_bfloat162 h1 = __floats2bfloat162_rn(v.z, v.w);
    __nv_bfloat162 l0 = __floats2bfloat162_rn(v.x - __bfloat162float(h0.x),
                                              v.y - __bfloat162float(h0.y));
    __nv_bfloat162 l1 = __floats2bfloat162_rn(v.z - __bfloat162float(h1.x),
                                              v.w - __bfloat162float(h1.y));
    uint32_t o = sw_off(row, col * 2);
    ull hv = (ull)(*(uint32_t*)&h0) | ((ull)(*(uint32_t*)&h1) << 32);
    ull lv = (ull)(*(uint32_t*)&l0) | ((ull)(*(uint32_t*)&l1) << 32);
    *(ull*)(hiB + o) = hv;
    *(ull*)(loB + o) = lv;
}

// ---- prep: W [256][128] f32 -> swizzled bf16 hi/lo W^T images per k-phase ----
__global__ void w_prep(const float* __restrict__ W, unsigned char* __restrict__ wt) {
    int i = blockIdx.x * blockDim.x + threadIdx.x;   // 32768 elements
    if (i >= 256 * 128) return;
    int k = i >> 7, n = i & 127;
    float x = W[(size_t)k * 128 + n];
    __nv_bfloat16 h = __float2bfloat16_rn(x);
    __nv_bfloat16 l = __float2bfloat16_rn(x - __bfloat162float(h));
    int phase = k >> 7, kk = k & 127;
    uint32_t o = sw_off(n, kk * 2);
    *(__nv_bfloat16*)(wt + phase * 65536 + o) = h;
    *(__nv_bfloat16*)(wt + phase * 65536 + 32768 + o) = l;
}

template <bool RELU>
__global__ void __launch_bounds__(NTHREADS, 1)
sage_layer(const float* __restrict__ h_in,
           const int*   __restrict__ nidx,
           const unsigned char* __restrict__ wt,   // prepped W image (131072 B)
           const float* __restrict__ bias,
           float*       __restrict__ out)
{
    extern __shared__ char smem_c[];
    const uint32_t sb = smem_u32(smem_c);
    const int tid  = threadIdx.x;
    const int wid  = tid >> 5;
    const int lane = tid & 31;

    if (tid < 128) ((float*)(smem_c + OFF_BIAS))[tid] = bias[tid];
    float* bias_s = (float*)(smem_c + OFF_BIAS);

    for (int tile = blockIdx.x; tile < TILES; tile += gridDim.x) {
        const int base = tile * BM;
        __syncthreads();   // smem reuse safe: prev tile fully consumed; bias visible

        if (wid >= 8) {
            // ================= GATHER WARPS (8-15) =================
            const int g = wid - 8;                      // owns nodes g*16..g*16+15
            int* myidx = (int*)(smem_c + OFF_IDX) + g * 256;
            {
                const int4* src = (const int4*)(nidx + (size_t)(base + g * 16) * KNE);
                #pragma unroll
                for (int q = 0; q < 2; q++) {
                    int qi = lane * 2 + q;              // int4 index 0..63
                    int node = qi >> 2;
                    int4 v = make_int4(0, 0, 0, 0);
                    if (base + g * 16 + node < N_NODES) v = src[qi];
                    ((int4*)myidx)[qi] = v;
                }
                __syncwarp();
            }
            char* aggHi = smem_c + OFF_AGG;
            char* aggLo = aggHi + 32768;
            #pragma unroll 1
            for (int grp = 0; grp < 4; grp++) {
                const int* ip = myidx + grp * 4 * KNE;
                ull ax[4], ay[4];
                #pragma unroll
                for (int t = 0; t < 4; t++) { ax[t] = 0; ay[t] = 0; }
                float4 buf[2][4];
                #pragma unroll
                for (int s = 0; s < 2; s++)
                    #pragma unroll
                    for (int t = 0; t < 4; t++)
                        buf[s][t] = ((const float4*)(h_in + (size_t)ip[t * KNE + s] * D))[lane];
                #pragma unroll
                for (int s = 0; s < 16; s++) {
                    const int slot = s & 1;
                    #pragma unroll
                    for (int t = 0; t < 4; t++) {
                        ulonglong2 p = *(ulonglong2*)&buf[slot][t];
                        ax[t] = add2(ax[t], p.x);
                        ay[t] = add2(ay[t], p.y);
                    }
                    if (s < 14) {
                        #pragma unroll
                        for (int t = 0; t < 4; t++)
                            buf[slot][t] =
                                ((const float4*)(h_in + (size_t)ip[t * KNE + s + 2] * D))[lane];
                    }
                }
                int nb = g * 16 + grp * 4;
                #pragma unroll
                for (int t = 0; t < 4; t++) {
                    float x0, x1, x2, x3;
                    unpack2(ax[t], x0, x1); unpack2(ay[t], x2, x3);
                    split_store4(aggHi, aggLo, nb + t, lane * 4,
                                 make_float4(x0 * 0.0625f, x1 * 0.0625f,
                                             x2 * 0.0625f, x3 * 0.0625f));
                }
            }
            BAR_ARRIVE(2, 512);                         // A_agg ready
        } else {
            // ================= MMA WARPS (0-7) =================
            // load W phase-0 image (plain copy) + self features (split)
            {
                const float4* src = (const float4*)wt;
                float4* dst = (float4*)(smem_c + OFF_W);
                #pragma unroll 4
                for (int i = tid; i < 4096; i += 256) dst[i] = src[i];
            }
            {
                char* selfHi = smem_c + OFF_SELF;
                char* selfLo = selfHi + 32768;
                #pragma unroll 2
                for (int i = tid; i < BM * 32; i += 256) {
                    int row = i >> 5, c4 = i & 31;
                    if (base + row < N_NODES) {
                        float4 v = ((const float4*)(h_in + (size_t)(base + row) * D))[c4];
                        split_store4(selfHi, selfLo, row, c4 * 4, v);
                    }
                }
            }
            BAR_SYNC(1, 256);

            float acc[16][4];
            #pragma unroll
            for (int nt = 0; nt < 16; nt++)
                #pragma unroll
                for (int j = 0; j < 4; j++) acc[nt][j] = 0.0f;

            const int mrow = wid * 16;
            const uint32_t wHi = sb + OFF_W, wLo = wHi + 32768;

            // ---- phase computation over one A tile (K=128) ----
            auto mma_phase = [&](uint32_t aHi, uint32_t aLo) {
                #pragma unroll 1
                for (int kc = 0; kc < 8; kc++) {
                    int arow = mrow + (lane & 15);
                    uint32_t aoff = sw_off(arow, (kc * 2 + (lane >> 4)) * 16);
                    uint32_t ahi[4], alo[4];
                    ldsm4(ahi, aHi + aoff);
                    ldsm4(alo, aLo + aoff);
                    #pragma unroll
                    for (int nt = 0; nt < 16; nt++) {
                        int brow = nt * 8 + (lane & 7);
                        uint32_t boff = sw_off(brow, (kc * 2 + ((lane >> 3) & 1)) * 16);
                        uint32_t bhi[2], blo[2];
                        ldsm2(bhi, wHi + boff);
                        ldsm2(blo, wLo + boff);
                        mma_bf16(acc[nt], ahi, bhi);
                        mma_bf16(acc[nt], ahi, blo);
                        mma_bf16(acc[nt], alo, bhi);
                    }
                }
            };

            mma_phase(sb + OFF_SELF, sb + OFF_SELF + 32768);   // phase 1 (self)
            BAR_SYNC(1, 256);                                   // done reading W0
            {
                const float4* src = (const float4*)(wt + 65536);
                float4* dst = (float4*)(smem_c + OFF_W);
                #pragma unroll 4
                for (int i = tid; i < 4096; i += 256) dst[i] = src[i];
            }
            BAR_SYNC(1, 256);                                   // W1 loaded
            BAR_SYNC(2, 512);                                   // A_agg ready
            mma_phase(sb + OFF_AGG, sb + OFF_AGG + 32768);      // phase 2 (agg)

            // ---- epilogue: +bias, relu, store ----
            const int qrow = mrow + (lane >> 2);
            const int c0 = (lane & 3) * 2;
            #pragma unroll
            for (int half = 0; half < 2; half++) {
                int r = base + qrow + half * 8;
                if (r < N_NODES) {
                    float* orow = out + (size_t)r * D + c0;
                    #pragma unroll
                    for (int nt = 0; nt < 16; nt++) {
                        float v0 = acc[nt][half * 2]     + bias_s[nt * 8 + c0];
                        float v1 = acc[nt][half * 2 + 1] + bias_s[nt * 8 + c0 + 1];
                        if (RELU) { v0 = fmaxf(v0, 0.0f); v1 = fmaxf(v1, 0.0f); }
                        *(float2*)(orow + nt * 8) = make_float2(v0, v1);
                    }
                }
            }
        }
    }
}

extern "C" void kernel_launch(void* const* d_in, const int* in_sizes, int n_in,
                              void* d_out, int out_size) {
    const float* feats = (const float*)d_in[0];
    const int*   nidx  = (const int*)d_in[1];
    const float* Ws    = (const float*)d_in[2];
    const float* bs    = (const float*)d_in[3];
    float*       out   = (float*)d_out;

    void* p = nullptr;
    cudaGetSymbolAddress(&p, g_h);
    float* h1 = (float*)p;
    cudaGetSymbolAddress(&p, g_wt);
    unsigned char* wt = (unsigned char*)p;

    cudaFuncSetAttribute(sage_layer<true>,  cudaFuncAttributeMaxDynamicSharedMemorySize, SMEM_TOTAL);
    cudaFuncSetAttribute(sage_layer<false>, cudaFuncAttributeMaxDynamicSharedMemorySize, SMEM_TOTAL);

    // layer 0
    w_prep<<<64, 512>>>(Ws, wt);
    sage_layer<true><<<GRID, NTHREADS, SMEM_TOTAL>>>(feats, nidx, wt, bs, h1);
    // layer 1
    w_prep<<<64, 512>>>(Ws + 256 * 128, wt);
    sage_layer<false><<<GRID, NTHREADS, SMEM_TOTAL>>>(
        h1, nidx + (size_t)N_NODES * KNE, wt, bs + 128, out);
}

// round 12
// speedup vs baseline: 1.8468x; 1.1680x over previous
#include <cuda_runtime.h>
#include <cuda_bf16.h>
#include <cstdint>

// GraphSAGE on GB300 (sm_103a harness, PTX sm_103 base — no tcgen05).
// R11: mma.sync bf16 split path, BM=64 with BOTH W phases resident in smem,
// cross-tile pipelining (double-buffered A_agg; gather warps run one tile
// ahead), B fragments via ldsm4 (half the LDSM), idx via LDG+shfl (no smem).

#define N_NODES 100000
#define D 128
#define KNE 16
#define BM 64
#define NTHREADS 512
#define TILES ((N_NODES + BM - 1) / BM)   // 1563
#define GRID 152

// smem byte offsets
#define OFF_W     0                        // [phase][hi|lo] 4 x 32768 = 131072
#define OFF_SELF  131072                   // hi 16384 | lo 16384
#define OFF_AGG   163840                   // 2 buffers x (hi 16384 | lo 16384)
#define OFF_BIAS  229376
#define SMEM_TOTAL 229888

typedef unsigned long long ull;

__device__ float g_h[(size_t)N_NODES * D];
__device__ __align__(16) unsigned char g_wt[131072];   // prepped W image

// ---------------- helpers ----------------
__device__ __forceinline__ uint32_t smem_u32(const void* p) {
    uint32_t a;
    asm("{ .reg .u64 t; cvta.to.shared.u64 t, %1; cvt.u32.u64 %0, t; }" : "=r"(a) : "l"(p));
    return a;
}
__device__ __forceinline__ ull add2(ull a, ull b) {
    ull r; asm("add.rn.f32x2 %0, %1, %2;" : "=l"(r) : "l"(a), "l"(b)); return r;
}
__device__ __forceinline__ void unpack2(ull v, float& lo, float& hi) {
    asm("mov.b64 {%0, %1}, %2;" : "=f"(lo), "=f"(hi) : "l"(v));
}
__device__ __forceinline__ void ldsm4(uint32_t* r, uint32_t addr) {
    asm volatile("ldmatrix.sync.aligned.m8n8.x4.shared.b16 {%0,%1,%2,%3}, [%4];"
        : "=r"(r[0]), "=r"(r[1]), "=r"(r[2]), "=r"(r[3]) : "r"(addr));
}
__device__ __forceinline__ void mma_bf16(float* d, const uint32_t* a, const uint32_t* b) {
    asm volatile("mma.sync.aligned.m16n8k16.row.col.f32.bf16.bf16.f32 "
        "{%0,%1,%2,%3}, {%4,%5,%6,%7}, {%8,%9}, {%0,%1,%2,%3};"
        : "+f"(d[0]), "+f"(d[1]), "+f"(d[2]), "+f"(d[3])
        : "r"(a[0]), "r"(a[1]), "r"(a[2]), "r"(a[3]), "r"(b[0]), "r"(b[1]));
}
#define BAR_SYNC(id, n)   asm volatile("bar.sync %0, %1;"   :: "r"(id), "r"(n) : "memory")
#define BAR_ARRIVE(id, n) asm volatile("bar.arrive %0, %1;" :: "r"(id), "r"(n) : "memory")

// XOR-swizzled byte offset in a [rows][256 B] tile: bits 4-6 ^= row&7.
__device__ __host__ __forceinline__ uint32_t sw_off(int row, int byte_in_row) {
    return (uint32_t)(row * 256 + (byte_in_row ^ ((row & 7) << 4)));
}

__device__ __forceinline__ void split_store4(char* hiB, char* loB, int row, int col, float4 v) {
    __nv_bfloat162 h0 = __floats2bfloat162_rn(v.x, v.y);
    __nv_bfloat162 h1 = __floats2bfloat162_rn(v.z, v.w);
    __nv_bfloat162 l0 = __floats2bfloat162_rn(v.x - __bfloat162float(h0.x),
                                              v.y - __bfloat162float(h0.y));
    __nv_bfloat162 l1 = __floats2bfloat162_rn(v.z - __bfloat162float(h1.x),
                                              v.w - __bfloat162float(h1.y));
    uint32_t o = sw_off(row, col * 2);
    ull hv = (ull)(*(uint32_t*)&h0) | ((ull)(*(uint32_t*)&h1) << 32);
    ull lv = (ull)(*(uint32_t*)&l0) | ((ull)(*(uint32_t*)&l1) << 32);
    *(ull*)(hiB + o) = hv;
    *(ull*)(loB + o) = lv;
}

// prep: W [256][128] f32 -> swizzled bf16 hi/lo W^T images per k-phase
__global__ void w_prep(const float* __restrict__ W, unsigned char* __restrict__ wt) {
    int i = blockIdx.x * blockDim.x + threadIdx.x;
    if (i >= 256 * 128) return;
    int k = i >> 7, n = i & 127;
    float x = W[(size_t)k * 128 + n];
    __nv_bfloat16 h = __float2bfloat16_rn(x);
    __nv_bfloat16 l = __float2bfloat16_rn(x - __bfloat162float(h));
    int phase = k >> 7, kk = k & 127;
    uint32_t o = sw_off(n, kk * 2);
    *(__nv_bfloat16*)(wt + phase * 65536 + o) = h;
    *(__nv_bfloat16*)(wt + phase * 65536 + 32768 + o) = l;
}

template <bool RELU>
__global__ void __launch_bounds__(NTHREADS, 1)
sage_layer(const float* __restrict__ h_in,
           const int*   __restrict__ nidx,
           const unsigned char* __restrict__ wt,
           const float* __restrict__ bias,
           float*       __restrict__ out)
{
    extern __shared__ char smem_c[];
    const uint32_t sb = smem_u32(smem_c);
    const int tid  = threadIdx.x;
    const int wid  = tid >> 5;
    const int lane = tid & 31;

    // ---- one-time: W (both phases) + bias into smem ----
    {
        const float4* src = (const float4*)wt;
        float4* dst = (float4*)(smem_c + OFF_W);
        #pragma unroll 4
        for (int i = tid; i < 8192; i += NTHREADS) dst[i] = src[i];
    }
    if (tid < 128) ((float*)(smem_c + OFF_BIAS))[tid] = bias[tid];
    float* bias_s = (float*)(smem_c + OFF_BIAS);
    __syncthreads();

    int it = 0;
    for (int tile = blockIdx.x; tile < TILES; tile += gridDim.x, it++) {
        const int base = tile * BM;
        const int buf  = it & 1;

        if (wid >= 8) {
            // ================= GATHER WARPS (8-15): produce A_agg[buf] ======
            const int g = wid - 8;                       // nodes g*8 .. g*8+7
            if (it >= 2) BAR_SYNC(4 + buf, 512);         // agg[buf] free
            char* aggHi = smem_c + OFF_AGG + buf * 32768;
            char* aggLo = aggHi + 16384;
            #pragma unroll
            for (int grp = 0; grp < 2; grp++) {
                const int n0g = g * 8 + grp * 4;         // local node base
                const int* gsrc = nidx + (size_t)(base + n0g) * KNE;
                int v0 = 0, v1 = 0;
                if (base + n0g + (lane >> 4) < N_NODES)     v0 = gsrc[lane];
                if (base + n0g + 2 + (lane >> 4) < N_NODES) v1 = gsrc[32 + lane];

                ull ax[4], ay[4];
                #pragma unroll
                for (int t = 0; t < 4; t++) { ax[t] = 0; ay[t] = 0; }
                float4 rbuf[2][4];
                #pragma unroll
                for (int s = 0; s < 2; s++)
                    #pragma unroll
                    for (int t = 0; t < 4; t++) {
                        const int f = t * 16 + s;
                        int id = __shfl_sync(0xffffffffu, (f < 32) ? v0 : v1, f & 31);
                        rbuf[s][t] = ((const float4*)(h_in + (size_t)id * D))[lane];
                    }
                #pragma unroll
                for (int s = 0; s < 16; s++) {
                    const int slot = s & 1;
                    #pragma unroll
                    for (int t = 0; t < 4; t++) {
                        ulonglong2 p = *(ulonglong2*)&rbuf[slot][t];
                        ax[t] = add2(ax[t], p.x);
                        ay[t] = add2(ay[t], p.y);
                    }
                    if (s < 14) {
                        #pragma unroll
                        for (int t = 0; t < 4; t++) {
                            const int f = t * 16 + s + 2;
                            int id = __shfl_sync(0xffffffffu, (f < 32) ? v0 : v1, f & 31);
                            rbuf[slot][t] = ((const float4*)(h_in + (size_t)id * D))[lane];
                        }
                    }
                }
                #pragma unroll
                for (int t = 0; t < 4; t++) {
                    float x0, x1, x2, x3;
                    unpack2(ax[t], x0, x1); unpack2(ay[t], x2, x3);
                    split_store4(aggHi, aggLo, n0g + t, lane * 4,
                                 make_float4(x0 * 0.0625f, x1 * 0.0625f,
                                             x2 * 0.0625f, x3 * 0.0625f));
                }
            }
            BAR_ARRIVE(2 + buf, 512);                    // agg[buf] produced
        } else {
            // ================= MMA WARPS (0-7) =================
            const int rowBlk = (wid & 3) * 16;
            const int colBlk = (wid >> 2) * 64;

            // self features -> smem split tile
            {
                char* selfHi = smem_c + OFF_SELF;
                char* selfLo = selfHi + 16384;
                #pragma unroll
                for (int q = 0; q < 8; q++) {
                    int i = tid + q * 256;               // 0..2047
                    int row = i >> 5, c4 = i & 31;
                    if (base + row < N_NODES) {
                        float4 v = ((const float4*)(h_in + (size_t)(base + row) * D))[c4];
                        split_store4(selfHi, selfLo, row, c4 * 4, v);
                    }
                }
            }
            BAR_SYNC(1, 256);                            // self ready (MMA-only)

            float acc[8][4];
            #pragma unroll
            for (int nt = 0; nt < 8; nt++)
                #pragma unroll
                for (int j = 0; j < 4; j++) acc[nt][j] = 0.0f;

            const uint32_t wBase = sb + OFF_W;
            const int arow  = rowBlk + (lane & 15);
            const int akoff = (lane >> 4) * 16;          // k-half byte offset
            const int brow  = colBlk + ((lane >> 4) & 1) * 8 + (lane & 7);
            const int bkoff = ((lane >> 3) & 1) * 16;

            auto mma_phase = [&](uint32_t aTile, uint32_t wHi) {
                const uint32_t aHi = aTile, aLo = aTile + 16384;
                const uint32_t wLo = wHi + 32768;
                #pragma unroll
                for (int kc = 0; kc < 8; kc++) {
                    const int kb = kc * 32;
                    uint32_t ahr[4], alr[4];
                    uint32_t ao = sw_off(arow, kb + akoff);
                    ldsm4(ahr, aHi + ao);
                    ldsm4(alr, aLo + ao);
                    uint32_t bh[4][4], bl[4][4];
                    #pragma unroll
                    for (int ntp = 0; ntp < 4; ntp++) {
                        uint32_t bo = sw_off(brow + ntp * 16, kb + bkoff);
                        ldsm4(bh[ntp], wHi + bo);
                        ldsm4(bl[ntp], wLo + bo);
                    }
                    #pragma unroll
                    for (int ntp = 0; ntp < 4; ntp++) {
                        mma_bf16(acc[2 * ntp],     ahr, bh[ntp]);
                        mma_bf16(acc[2 * ntp],     ahr, bl[ntp]);
                        mma_bf16(acc[2 * ntp],     alr, bh[ntp]);
                        mma_bf16(acc[2 * ntp + 1], ahr, bh[ntp] + 2);
                        mma_bf16(acc[2 * ntp + 1], ahr, bl[ntp] + 2);
                        mma_bf16(acc[2 * ntp + 1], alr, bh[ntp] + 2);
                    }
                }
            };

            mma_phase(sb + OFF_SELF, wBase);             // phase 1 (self, W0)
            BAR_SYNC(1, 256);                            // all MMA warps done w/ self
            BAR_SYNC(2 + buf, 512);                      // agg[buf] produced
            mma_phase(sb + OFF_AGG + buf * 32768, wBase + 65536);  // phase 2
            BAR_ARRIVE(4 + buf, 512);                    // agg[buf] consumed

            // epilogue
            const int qrow = rowBlk + (lane >> 2);
            const int c0 = (lane & 3) * 2;
            #pragma unroll
            for (int half = 0; half < 2; half++) {
                int r = base + qrow + half * 8;
                if (r < N_NODES) {
                    float* orow = out + (size_t)r * D + colBlk + c0;
                    #pragma unroll
                    for (int nt = 0; nt < 8; nt++) {
                        float v0 = acc[nt][half * 2]     + bias_s[colBlk + nt * 8 + c0];
                        float v1 = acc[nt][half * 2 + 1] + bias_s[colBlk + nt * 8 + c0 + 1];
                        if (RELU) { v0 = fmaxf(v0, 0.0f); v1 = fmaxf(v1, 0.0f); }
                        *(float2*)(orow + nt * 8) = make_float2(v0, v1);
                    }
                }
            }
        }
    }
}

extern "C" void kernel_launch(void* const* d_in, const int* in_sizes, int n_in,
                              void* d_out, int out_size) {
    const float* feats = (const float*)d_in[0];
    const int*   nidx  = (const int*)d_in[1];
    const float* Ws    = (const float*)d_in[2];
    const float* bs    = (const float*)d_in[3];
    float*       out   = (float*)d_out;

    void* p = nullptr;
    cudaGetSymbolAddress(&p, g_h);
    float* h1 = (float*)p;
    cudaGetSymbolAddress(&p, g_wt);
    unsigned char* wt = (unsigned char*)p;

    cudaFuncSetAttribute(sage_layer<true>,  cudaFuncAttributeMaxDynamicSharedMemorySize, SMEM_TOTAL);
    cudaFuncSetAttribute(sage_layer<false>, cudaFuncAttributeMaxDynamicSharedMemorySize, SMEM_TOTAL);

    // layer 0
    w_prep<<<64, 512>>>(Ws, wt);
    sage_layer<true><<<GRID, NTHREADS, SMEM_TOTAL>>>(feats, nidx, wt, bs, h1);
    // layer 1
    w_prep<<<64, 512>>>(Ws + 256 * 128, wt);
    sage_layer<false><<<GRID, NTHREADS, SMEM_TOTAL>>>(
        h1, nidx + (size_t)N_NODES * KNE, wt, bs + 128, out);
}